// round 13
// baseline (speedup 1.0000x reference)
#include <cuda_runtime.h>
#include <math.h>
#include <stdint.h>

#define NN      50000
#define NE      800000
#define NG      500
#define DIM     64
#define HID     256
#define NCLS    2000
#define NAT     100
#define TABLE_N 8193
#define CUTOFF  5.0f

#define FLAG_BETA  1
#define FLAG_RELUA 2

// ---------------- scratch (device globals; no allocation allowed) ----------
__device__ float g_node[NN * DIM];
__device__ float g_newnode[NN * DIM];   // also reused as t-buffer
__device__ float g_agg[NN * DIM];
__device__ float g_atom[NN * HID];
__device__ float g_res[NN * HID];
__device__ float g_table[3 * TABLE_N * DIM];
__device__ float g_gsum[NG * HID];
__device__ float g_gcnt[NG];
__device__ float g_gmean[NG * HID];

// ---------------- activations ---------------------------------------------
__device__ __forceinline__ float softplusf(float x) {
    return fmaxf(x, 0.0f) + log1pf(expf(-fabsf(x)));
}
__device__ __forceinline__ float sp2f(float x) {       // 2*softplus(0.5x)
    return 2.0f * softplusf(0.5f * x);
}
__device__ __forceinline__ float sspf(float x) {       // softplus(x) - ln2
    return softplusf(x) - 0.69314718055994531f;
}

// ---------------- f32x2 packed math ----------------------------------------
__device__ __forceinline__ uint64_t dup2(float v) {
    uint64_t r;
    asm("mov.b64 %0, {%1, %1};" : "=l"(r) : "f"(v));
    return r;
}
__device__ __forceinline__ void ffma2(uint64_t& d, uint64_t a, uint64_t b) {
    asm("fma.rn.f32x2 %0, %1, %2, %0;" : "+l"(d) : "l"(a), "l"(b));
}
__device__ __forceinline__ void unpack2(uint64_t v, float& lo, float& hi) {
    asm("mov.b64 {%0, %1}, %2;" : "=f"(lo), "=f"(hi) : "l"(v));
}

// ---------------- tiny utility kernels -------------------------------------
__global__ void zero_kernel(float* __restrict__ p, int n) {
    int i = blockIdx.x * blockDim.x + threadIdx.x;
    if (i < n) p[i] = 0.0f;
}

__global__ void embed_kernel(const int* __restrict__ types,
                             const float* __restrict__ emb,
                             float* __restrict__ node) {
    int i = blockIdx.x * blockDim.x + threadIdx.x;
    if (i >= NN * DIM) return;
    int n = i >> 6;      // /64
    int c = i & 63;
    node[i] = emb[types[n] * DIM + c];
}

// eh(d) table per layer: sp2(sp2(rbf(d)@cf1 + b1)@cf2 + b2)
__global__ void build_table_kernel(const float* __restrict__ cf1_w,  // [3,5,64]
                                   const float* __restrict__ cf1_b,  // [3,64]
                                   const float* __restrict__ cf2_w,  // [3,64,64]
                                   const float* __restrict__ cf2_b,  // [3,64]
                                   float* __restrict__ table) {
    __shared__ float h[DIM];
    int b = blockIdx.x;
    int layer = b / TABLE_N;
    int ent   = b % TABLE_N;
    int j = threadIdx.x;

    const float gap = CUTOFF / 4.0f;                 // linspace(0,5,5) gap = 1.25
    float d = (float)ent * (CUTOFF / (float)(TABLE_N - 1));

    float rbf[5];
#pragma unroll
    for (int r = 0; r < 5; r++) {
        float t = d - (float)r * gap;
        rbf[r] = expf(-(1.0f / gap) * t * t);
    }
    float acc = cf1_b[layer * DIM + j];
#pragma unroll
    for (int r = 0; r < 5; r++)
        acc += rbf[r] * cf1_w[(layer * 5 + r) * DIM + j];
    h[j] = sp2f(acc);
    __syncthreads();

    float acc2 = cf2_b[layer * DIM + j];
    const float* W = cf2_w + layer * DIM * DIM;
#pragma unroll 8
    for (int k = 0; k < DIM; k++)
        acc2 += h[k] * W[k * DIM + j];
    table[(layer * TABLE_N + ent) * DIM + j] = sp2f(acc2);
}

// 16 lanes per edge; each lane handles 4 consecutive floats (float4, 128-bit)
__global__ void edge_kernel(const int* __restrict__ src,
                            const int* __restrict__ dst,
                            const float* __restrict__ dist,
                            const float* __restrict__ newnode,
                            const float* __restrict__ table,   // [TABLE_N,64]
                            float* __restrict__ agg) {
    int idx = blockIdx.x * blockDim.x + threadIdx.x;
    int e = idx >> 4;
    if (e >= NE) return;
    int lane = idx & 15;

    int s = __ldg(src + e);
    int t = __ldg(dst + e);
    float dd = __ldg(dist + e);

    float f = dd * ((float)(TABLE_N - 1) / CUTOFF);
    f = fminf(fmaxf(f, 0.0f), (float)(TABLE_N - 1));
    int i0 = (int)f;
    if (i0 > TABLE_N - 2) i0 = TABLE_N - 2;
    float fr = f - (float)i0;

    const float4* nn = (const float4*)(newnode + (size_t)s * DIM);
    const float4* tb = (const float4*)(table + (size_t)i0 * DIM);

    float4 a  = nn[lane];
    float4 u0 = tb[lane];          // row i0
    float4 u1 = tb[lane + 16];     // row i0+1 (adjacent, +64 floats)

    float m0 = a.x * fmaf(fr, u1.x - u0.x, u0.x);
    float m1 = a.y * fmaf(fr, u1.y - u0.y, u0.y);
    float m2 = a.z * fmaf(fr, u1.z - u0.z, u0.z);
    float m3 = a.w * fmaf(fr, u1.w - u0.w, u0.w);

    float* out = agg + (size_t)t * DIM + lane * 4;
    asm volatile("red.global.add.v4.f32 [%0], {%1, %2, %3, %4};"
                 :: "l"(out), "f"(m0), "f"(m1), "f"(m2), "f"(m3) : "memory");
}

// graph pooling: accumulate res rows into per-graph sums
__global__ void pool_kernel(const int* __restrict__ gid,
                            const float* __restrict__ res,
                            float* __restrict__ gsum) {
    int idx = blockIdx.x * blockDim.x + threadIdx.x;   // NN * 128 threads
    if (idx >= NN * (HID / 2)) return;
    int n  = idx >> 7;        // /128
    int c2 = idx & 127;
    int g = __ldg(gid + n);
    const float2 v = ((const float2*)(res + (size_t)n * HID))[c2];
    float* out = gsum + (size_t)g * HID + c2 * 2;
    asm volatile("red.global.add.v2.f32 [%0], {%1, %2};"
                 :: "l"(out), "f"(v.x), "f"(v.y) : "memory");
}

__global__ void count_kernel(const int* __restrict__ gid, float* __restrict__ gcnt) {
    int i = blockIdx.x * blockDim.x + threadIdx.x;
    if (i < NN) atomicAdd(&gcnt[gid[i]], 1.0f);
}

__global__ void mean_kernel(const float* __restrict__ gsum,
                            const float* __restrict__ gcnt,
                            float* __restrict__ gmean) {
    int i = blockIdx.x * blockDim.x + threadIdx.x;
    if (i >= NG * HID) return;
    int g = i >> 8;   // /256
    gmean[i] = gsum[i] / fmaxf(gcnt[g], 1.0f);
}

// ---------------- SGEMM: f32x2, dup-B smem, 8x8 microtile, u64 LDS ----------
// C = act(A@B + bias) [+C].  A:[M,K] rm, B:[K,N] rm.  K % 32 == 0.
// BM=256, BN=64, KC=32, 256 threads. Inner loop reads smem DIRECTLY as
// ulonglong2 (aligned even/odd reg pairs) so FFMA2 operands need no MOVs.
#define BM 256
#define BN 64
#define KC 32
#define AP (BM + 4)     // padded As row stride; 260*4B = 1040B, 16B-aligned rows

__global__ __launch_bounds__(256)
void sgemm_kernel(const float* __restrict__ A,
                  const float* __restrict__ B,
                  const float* __restrict__ bias,
                  float* __restrict__ C,
                  int M, int N, int K, int act, int flags) {
    __shared__ float As[KC][AP];        // k-major (transposed)
    __shared__ float Bd[KC][BN * 2];    // duplicated: Bd[k][2n]=Bd[k][2n+1]=B[k][n]

    int bm = blockIdx.y * BM;
    int bn = blockIdx.x * BN;
    int tid = threadIdx.x;
    int tr = tid >> 3;             // 0..31
    int tc = tid & 7;              // 0..7
    int row0 = tr * 8;

    uint64_t acc[4][8];            // [row-pair][col]
#pragma unroll
    for (int i = 0; i < 4; i++)
#pragma unroll
        for (int j = 0; j < 8; j++) acc[i][j] = 0ull;

    const bool reluA = (flags & FLAG_RELUA) != 0;

    for (int k0 = 0; k0 < K; k0 += KC) {
        // ---- load A chunk (BM x KC): 8 float4 per thread, transposed store ----
#pragma unroll
        for (int q = 0; q < 8; q++) {
            int m  = q * 32 + (tid >> 3);
            int ks = (tid & 7) * 4;
            int gr = bm + m;
            float4 v = make_float4(0.f, 0.f, 0.f, 0.f);
            if (gr < M)
                v = *(const float4*)(A + (size_t)gr * K + k0 + ks);
            if (reluA) {
                v.x = fmaxf(v.x, 0.f); v.y = fmaxf(v.y, 0.f);
                v.z = fmaxf(v.z, 0.f); v.w = fmaxf(v.w, 0.f);
            }
            As[ks + 0][m] = v.x;
            As[ks + 1][m] = v.y;
            As[ks + 2][m] = v.z;
            As[ks + 3][m] = v.w;
        }
        // ---- load B chunk duplicated (KC x BN src): 8 floats per thread ----
        {
            int kk = tid >> 3;              // 0..31
            int n0 = (tid & 7) * 8;         // 0,8,...,56
            const float* Brow = B + (size_t)(k0 + kk) * N + bn;
#pragma unroll
            for (int p = 0; p < 4; p++) {
                int n = n0 + p * 2;
                float x = 0.f, y = 0.f;
                int gc = bn + n;
                if (gc + 1 < N) {
                    float2 v2 = *(const float2*)(Brow + n);
                    x = v2.x; y = v2.y;
                } else {
                    if (gc < N) x = Brow[n];
                }
                *(uint64_t*)&Bd[kk][2 * n]     = dup2(x);
                *(uint64_t*)&Bd[kk][2 * n + 2] = dup2(y);
            }
        }
        __syncthreads();

#pragma unroll
        for (int kk = 0; kk < KC; kk++) {
            // A row-pairs read directly as packed uint64 pairs (no MOVs)
            ulonglong2 a01 = *(const ulonglong2*)&As[kk][row0];      // rows r0..r0+3
            ulonglong2 a23 = *(const ulonglong2*)&As[kk][row0 + 4];  // rows r0+4..r0+7
            uint64_t b[8];
#pragma unroll
            for (int j = 0; j < 4; j++) {
                ulonglong2 bv = *(const ulonglong2*)&Bd[kk][j * 32 + tc * 4];
                b[j * 2]     = bv.x;   // dup'd col j*16+tc*2
                b[j * 2 + 1] = bv.y;   // dup'd col j*16+tc*2+1
            }
#pragma unroll
            for (int c = 0; c < 8; c++) {
                ffma2(acc[0][c], a01.x, b[c]);
                ffma2(acc[1][c], a01.y, b[c]);
                ffma2(acc[2][c], a23.x, b[c]);
                ffma2(acc[3][c], a23.y, b[c]);
            }
        }
        __syncthreads();
    }

    // ---- epilogue: 8 rows x 8 cols ----
#pragma unroll
    for (int rp = 0; rp < 4; rp++) {
#pragma unroll
        for (int h = 0; h < 2; h++) {
            int r = bm + row0 + rp * 2 + h;
            if (r >= M) continue;
            float vals[8];
#pragma unroll
            for (int c = 0; c < 8; c++) {
                float lo, hi;
                unpack2(acc[rp][c], lo, hi);
                vals[c] = h ? hi : lo;
            }
#pragma unroll
            for (int j = 0; j < 4; j++) {
                int c0 = bn + j * 16 + tc * 2;
#pragma unroll
                for (int u = 0; u < 2; u++) {
                    int c = c0 + u;
                    if (c >= N) continue;
                    float v = vals[j * 2 + u];
                    if (bias) v += bias[c];
                    if (act == 1) v = sp2f(v);
                    else if (act == 2) v = sspf(v);
                    if (flags & FLAG_BETA) v += C[(size_t)r * N + c];
                    C[(size_t)r * N + c] = v;
                }
            }
        }
    }
}

// ---------------- driver ----------------------------------------------------
static inline dim3 gemm_grid(int M, int N) {
    return dim3((N + BN - 1) / BN, (M + BM - 1) / BM);
}

extern "C" void kernel_launch(void* const* d_in, const int* in_sizes, int n_in,
                              void* d_out, int out_size) {
    const int*   node_types = (const int*)  d_in[0];
    const int*   edge_src   = (const int*)  d_in[1];
    const int*   edge_dst   = (const int*)  d_in[2];
    const int*   graph_ids  = (const int*)  d_in[3];
    const float* distance   = (const float*)d_in[4];
    const float* emb        = (const float*)d_in[5];
    const float* conv_w1    = (const float*)d_in[6];
    const float* cf1_w      = (const float*)d_in[7];
    const float* cf1_b      = (const float*)d_in[8];
    const float* cf2_w      = (const float*)d_in[9];
    const float* cf2_b      = (const float*)d_in[10];
    const float* nl2_w      = (const float*)d_in[11];
    const float* nl2_b      = (const float*)d_in[12];
    const float* nl3_w      = (const float*)d_in[13];
    const float* nl3_b      = (const float*)d_in[14];
    const float* d1_w       = (const float*)d_in[15];
    const float* d1_b       = (const float*)d_in[16];
    const float* d2_w       = (const float*)d_in[17];
    const float* d2_b       = (const float*)d_in[18];
    const float* cls_w      = (const float*)d_in[19];
    const float* cls_b      = (const float*)d_in[20];
    const float* ac_w       = (const float*)d_in[21];
    const float* ac_b       = (const float*)d_in[22];
    float* out = (float*)d_out;

    float *node, *newnode, *agg, *atom, *res, *table, *gsum, *gcnt, *gmean;
    cudaGetSymbolAddress((void**)&node,    g_node);
    cudaGetSymbolAddress((void**)&newnode, g_newnode);
    cudaGetSymbolAddress((void**)&agg,     g_agg);
    cudaGetSymbolAddress((void**)&atom,    g_atom);
    cudaGetSymbolAddress((void**)&res,     g_res);
    cudaGetSymbolAddress((void**)&table,   g_table);
    cudaGetSymbolAddress((void**)&gsum,    g_gsum);
    cudaGetSymbolAddress((void**)&gcnt,    g_gcnt);
    cudaGetSymbolAddress((void**)&gmean,   g_gmean);

    // node = emb[node_types]
    embed_kernel<<<(NN * DIM + 255) / 256, 256>>>(node_types, emb, node);

    // per-layer eh(d) lookup tables
    build_table_kernel<<<3 * TABLE_N, DIM>>>(cf1_w, cf1_b, cf2_w, cf2_b, table);

    dim3 g64 = gemm_grid(NN, DIM);
    for (int l = 0; l < 3; l++) {
        // newnode = node @ w1
        sgemm_kernel<<<g64, 256>>>(node, conv_w1 + (size_t)l * DIM * DIM,
                                   nullptr, newnode, NN, DIM, DIM, 0, 0);
        // agg = 0
        zero_kernel<<<(NN * DIM + 255) / 256, 256>>>(agg, NN * DIM);
        // agg[dst] += newnode[src] * eh(d)
        edge_kernel<<<(NE * 16 + 255) / 256, 256>>>(
            edge_src, edge_dst, distance, newnode,
            table + (size_t)l * TABLE_N * DIM, agg);
        // t = sp2(agg @ nl2 + b2)   (reuse newnode as t)
        sgemm_kernel<<<g64, 256>>>(agg, nl2_w + (size_t)l * DIM * DIM,
                                   nl2_b + l * DIM, newnode, NN, DIM, DIM, 1, 0);
        // node += t @ nl3 + b3
        sgemm_kernel<<<g64, 256>>>(newnode, nl3_w + (size_t)l * DIM * DIM,
                                   nl3_b + l * DIM, node, NN, DIM, DIM, 0, FLAG_BETA);
    }

    // atom = ssp(node @ d1 + b)
    sgemm_kernel<<<gemm_grid(NN, HID), 256>>>(node, d1_w, d1_b, atom,
                                              NN, HID, DIM, 2, 0);
    // res = atom @ d2 + b
    sgemm_kernel<<<gemm_grid(NN, HID), 256>>>(atom, d2_w, d2_b, res,
                                              NN, HID, HID, 0, 0);
    // atoms_preds = relu(res) @ ac + b   -> out[0 : NN*100]
    sgemm_kernel<<<gemm_grid(NN, NAT), 256>>>(res, ac_w, ac_b, out,
                                              NN, NAT, HID, 0, FLAG_RELUA);

    // graph pooling
    zero_kernel<<<(NG * HID + 255) / 256, 256>>>(gsum, NG * HID);
    zero_kernel<<<(NG + 255) / 256, 256>>>(gcnt, NG);
    pool_kernel<<<(NN * (HID / 2) + 255) / 256, 256>>>(graph_ids, res, gsum);
    count_kernel<<<(NN + 255) / 256, 256>>>(graph_ids, gcnt);
    mean_kernel<<<(NG * HID + 255) / 256, 256>>>(gsum, gcnt, gmean);

    // cls_preds = gmean @ cls_w + b -> out[NN*100 : ]
    sgemm_kernel<<<gemm_grid(NG, NCLS), 256>>>(gmean, cls_w, cls_b,
                                               out + (size_t)NN * NAT,
                                               NG, NCLS, HID, 0, 0);
}

// round 15
// speedup vs baseline: 1.6670x; 1.6670x over previous
#include <cuda_runtime.h>
#include <cuda_bf16.h>
#include <math.h>
#include <stdint.h>

#define NN      50000
#define NE      800000
#define NG      500
#define DIM     64
#define HID     256
#define NCLS    2000
#define NAT     100
#define TABLE_N 8193
#define CUTOFF  5.0f

#define FLAG_BETA  1
#define FLAG_RELUA 2

// ---------------- scratch (device globals; no allocation allowed) ----------
__device__ float g_node[NN * DIM];
__device__ float g_newnode[NN * DIM];   // also reused as t-buffer
__device__ float g_agg[NN * DIM];
__device__ float g_atom[NN * HID];
__device__ float g_res[NN * HID];
__device__ float g_table[3 * TABLE_N * DIM];
__device__ float g_gsum[NG * HID];
__device__ float g_gcnt[NG];
__device__ float g_gmean[NG * HID];

// ---------------- activations ---------------------------------------------
__device__ __forceinline__ float softplusf(float x) {
    return fmaxf(x, 0.0f) + log1pf(expf(-fabsf(x)));
}
__device__ __forceinline__ float sp2f(float x) {       // 2*softplus(0.5x)
    return 2.0f * softplusf(0.5f * x);
}
__device__ __forceinline__ float sspf(float x) {       // softplus(x) - ln2
    return softplusf(x) - 0.69314718055994531f;
}

// ---------------- tiny utility kernels -------------------------------------
__global__ void zero_kernel(float* __restrict__ p, int n) {
    int i = blockIdx.x * blockDim.x + threadIdx.x;
    if (i < n) p[i] = 0.0f;
}

__global__ void embed_kernel(const int* __restrict__ types,
                             const float* __restrict__ emb,
                             float* __restrict__ node) {
    int i = blockIdx.x * blockDim.x + threadIdx.x;
    if (i >= NN * DIM) return;
    int n = i >> 6;      // /64
    int c = i & 63;
    node[i] = emb[types[n] * DIM + c];
}

// eh(d) table per layer: sp2(sp2(rbf(d)@cf1 + b1)@cf2 + b2)
__global__ void build_table_kernel(const float* __restrict__ cf1_w,  // [3,5,64]
                                   const float* __restrict__ cf1_b,  // [3,64]
                                   const float* __restrict__ cf2_w,  // [3,64,64]
                                   const float* __restrict__ cf2_b,  // [3,64]
                                   float* __restrict__ table) {
    __shared__ float h[DIM];
    int b = blockIdx.x;
    int layer = b / TABLE_N;
    int ent   = b % TABLE_N;
    int j = threadIdx.x;

    const float gap = CUTOFF / 4.0f;                 // linspace(0,5,5) gap = 1.25
    float d = (float)ent * (CUTOFF / (float)(TABLE_N - 1));

    float rbf[5];
#pragma unroll
    for (int r = 0; r < 5; r++) {
        float t = d - (float)r * gap;
        rbf[r] = expf(-(1.0f / gap) * t * t);
    }
    float acc = cf1_b[layer * DIM + j];
#pragma unroll
    for (int r = 0; r < 5; r++)
        acc += rbf[r] * cf1_w[(layer * 5 + r) * DIM + j];
    h[j] = sp2f(acc);
    __syncthreads();

    float acc2 = cf2_b[layer * DIM + j];
    const float* W = cf2_w + layer * DIM * DIM;
#pragma unroll 8
    for (int k = 0; k < DIM; k++)
        acc2 += h[k] * W[k * DIM + j];
    table[(layer * TABLE_N + ent) * DIM + j] = sp2f(acc2);
}

// 16 lanes per edge; each lane handles 4 consecutive floats (float4, 128-bit)
__global__ void edge_kernel(const int* __restrict__ src,
                            const int* __restrict__ dst,
                            const float* __restrict__ dist,
                            const float* __restrict__ newnode,
                            const float* __restrict__ table,   // [TABLE_N,64]
                            float* __restrict__ agg) {
    int idx = blockIdx.x * blockDim.x + threadIdx.x;
    int e = idx >> 4;
    if (e >= NE) return;
    int lane = idx & 15;

    int s = __ldg(src + e);
    int t = __ldg(dst + e);
    float dd = __ldg(dist + e);

    float f = dd * ((float)(TABLE_N - 1) / CUTOFF);
    f = fminf(fmaxf(f, 0.0f), (float)(TABLE_N - 1));
    int i0 = (int)f;
    if (i0 > TABLE_N - 2) i0 = TABLE_N - 2;
    float fr = f - (float)i0;

    const float4* nn = (const float4*)(newnode + (size_t)s * DIM);
    const float4* tb = (const float4*)(table + (size_t)i0 * DIM);

    float4 a  = nn[lane];
    float4 u0 = tb[lane];          // row i0
    float4 u1 = tb[lane + 16];     // row i0+1 (adjacent, +64 floats)

    float m0 = a.x * fmaf(fr, u1.x - u0.x, u0.x);
    float m1 = a.y * fmaf(fr, u1.y - u0.y, u0.y);
    float m2 = a.z * fmaf(fr, u1.z - u0.z, u0.z);
    float m3 = a.w * fmaf(fr, u1.w - u0.w, u0.w);

    float* out = agg + (size_t)t * DIM + lane * 4;
    asm volatile("red.global.add.v4.f32 [%0], {%1, %2, %3, %4};"
                 :: "l"(out), "f"(m0), "f"(m1), "f"(m2), "f"(m3) : "memory");
}

// graph pooling: accumulate res rows into per-graph sums
__global__ void pool_kernel(const int* __restrict__ gid,
                            const float* __restrict__ res,
                            float* __restrict__ gsum) {
    int idx = blockIdx.x * blockDim.x + threadIdx.x;   // NN * 128 threads
    if (idx >= NN * (HID / 2)) return;
    int n  = idx >> 7;        // /128
    int c2 = idx & 127;
    int g = __ldg(gid + n);
    const float2 v = ((const float2*)(res + (size_t)n * HID))[c2];
    float* out = gsum + (size_t)g * HID + c2 * 2;
    asm volatile("red.global.add.v2.f32 [%0], {%1, %2};"
                 :: "l"(out), "f"(v.x), "f"(v.y) : "memory");
}

__global__ void count_kernel(const int* __restrict__ gid, float* __restrict__ gcnt) {
    int i = blockIdx.x * blockDim.x + threadIdx.x;
    if (i < NN) atomicAdd(&gcnt[gid[i]], 1.0f);
}

__global__ void mean_kernel(const float* __restrict__ gsum,
                            const float* __restrict__ gcnt,
                            float* __restrict__ gmean) {
    int i = blockIdx.x * blockDim.x + threadIdx.x;
    if (i >= NG * HID) return;
    int g = i >> 8;   // /256
    gmean[i] = gsum[i] / fmaxf(gcnt[g], 1.0f);
}

// ---------------- tensor-core GEMM: bf16 split (hi/lo), mma.m16n8k16 --------
// C = act(A@B + bias) [+C].  A:[M,K] rm, B:[K,N] rm.  K % 32 == 0.
// BM=128, BN=64, KC=32, 256 threads = 8 warps (warp_m = wid&3, warp_n = wid>>2).
// Per warp: 32x32 C tile = 2(m16) x 4(n8) mma tiles. Split A@B =
// AhiBhi + AhiBlo + AloBhi (3 mmas per tile pair; lo*lo dropped, ~4e-6 rel).
// smem holds fragments in mma register layout -> conflict-free LDS.128/LDS.64.
#define BM 128
#define BN 64
#define KC 32

__device__ __forceinline__ uint32_t bf16x2(float lo, float hi_) {
    __nv_bfloat162 h;
    h.x = __float2bfloat16(lo);
    h.y = __float2bfloat16(hi_);
    uint32_t r;
    memcpy(&r, &h, 4);
    return r;
}

__device__ __forceinline__ void mma16816(float* c, const uint32_t* a, const uint32_t* b) {
    asm volatile(
        "mma.sync.aligned.m16n8k16.row.col.f32.bf16.bf16.f32 "
        "{%0,%1,%2,%3}, {%4,%5,%6,%7}, {%8,%9}, {%0,%1,%2,%3};"
        : "+f"(c[0]), "+f"(c[1]), "+f"(c[2]), "+f"(c[3])
        : "r"(a[0]), "r"(a[1]), "r"(a[2]), "r"(a[3]), "r"(b[0]), "r"(b[1]));
}

__global__ __launch_bounds__(256)
void sgemm_kernel(const float* __restrict__ A,
                  const float* __restrict__ B,
                  const float* __restrict__ bias,
                  float* __restrict__ C,
                  int M, int N, int K, int act, int flags) {
    // fragment-layout smem: [mtile(8)][kstep(2)][lane(32)][slot]
    __shared__ uint32_t AsH[8][2][32][4];   // 8 KB
    __shared__ uint32_t AsL[8][2][32][4];   // 8 KB
    __shared__ uint32_t BsH[8][2][32][2];   // 4 KB
    __shared__ uint32_t BsL[8][2][32][2];   // 4 KB

    int bm = blockIdx.y * BM;
    int bn = blockIdx.x * BN;
    int tid  = threadIdx.x;
    int wid  = tid >> 5;
    int lane = tid & 31;
    int warp_m = wid & 3;       // 0..3 -> rows warp_m*32
    int warp_n = wid >> 2;      // 0..1 -> cols warp_n*32

    float acc[2][4][4];
#pragma unroll
    for (int i = 0; i < 2; i++)
#pragma unroll
        for (int j = 0; j < 4; j++)
#pragma unroll
            for (int c = 0; c < 4; c++) acc[i][j][c] = 0.0f;

    const bool reluA = (flags & FLAG_RELUA) != 0;

    for (int k0 = 0; k0 < K; k0 += KC) {
        // ---- A: 128 rows x 32 k; 4 float4 per thread; convert+scatter ----
#pragma unroll
        for (int q = 0; q < 4; q++) {
            int m  = q * 32 + (tid >> 3);     // 0..127
            int kf = (tid & 7) * 4;           // 0,4,...,28
            int gr = bm + m;
            float4 v = make_float4(0.f, 0.f, 0.f, 0.f);
            if (gr < M)
                v = *(const float4*)(A + (size_t)gr * K + k0 + kf);
            if (reluA) {
                v.x = fmaxf(v.x, 0.f); v.y = fmaxf(v.y, 0.f);
                v.z = fmaxf(v.z, 0.f); v.w = fmaxf(v.w, 0.f);
            }
            int mt = m >> 4, mh = m & 15;
            int ks = kf >> 4, kk = kf & 15;
            float xs[4] = {v.x, v.y, v.z, v.w};
#pragma unroll
            for (int p = 0; p < 2; p++) {
                int kh = kk + 2 * p;                        // even k within k16
                int l2 = (mh & 7) * 4 + ((kh & 7) >> 1);
                int s  = (mh >> 3) | ((kh >> 3) << 1);
                float x = xs[2 * p], y = xs[2 * p + 1];
                __nv_bfloat16 xh = __float2bfloat16(x);
                __nv_bfloat16 yh = __float2bfloat16(y);
                float xr = x - __bfloat162float(xh);
                float yr = y - __bfloat162float(yh);
                __nv_bfloat162 hh; hh.x = xh; hh.y = yh;
                uint32_t uh; memcpy(&uh, &hh, 4);
                AsH[mt][ks][l2][s] = uh;
                AsL[mt][ks][l2][s] = bf16x2(xr, yr);
            }
        }
        // ---- B: 32 k x 64 n as 1024 k-pairs; 4 per thread ----
#pragma unroll
        for (int r = 0; r < 4; r++) {
            int pi = tid + 256 * r;
            int n  = pi & 63;
            int k2 = (pi >> 6) << 1;          // even k 0..30
            int gc = bn + n;
            float x = 0.f, y = 0.f;
            if (gc < N) {
                int gk = k0 + k2;
                x = B[(size_t)gk * N + gc];
                y = B[(size_t)(gk + 1) * N + gc];
            }
            __nv_bfloat16 xh = __float2bfloat16(x);
            __nv_bfloat16 yh = __float2bfloat16(y);
            float xr = x - __bfloat162float(xh);
            float yr = y - __bfloat162float(yh);
            int nt = n >> 3, nh = n & 7;
            int ks = k2 >> 4, kk = k2 & 15;
            int l2 = nh * 4 + ((kk & 7) >> 1);
            int s  = kk >> 3;
            __nv_bfloat162 hh; hh.x = xh; hh.y = yh;
            uint32_t uh; memcpy(&uh, &hh, 4);
            BsH[nt][ks][l2][s] = uh;
            BsL[nt][ks][l2][s] = bf16x2(xr, yr);
        }
        __syncthreads();

        // ---- compute: 2 k16 steps ----
#pragma unroll
        for (int ks = 0; ks < 2; ks++) {
            uint32_t aH[2][4], aL[2][4], bH[4][2], bL[4][2];
#pragma unroll
            for (int mt2 = 0; mt2 < 2; mt2++) {
                int mt = warp_m * 2 + mt2;
                uint4 h = *(const uint4*)&AsH[mt][ks][lane][0];
                uint4 l = *(const uint4*)&AsL[mt][ks][lane][0];
                aH[mt2][0] = h.x; aH[mt2][1] = h.y; aH[mt2][2] = h.z; aH[mt2][3] = h.w;
                aL[mt2][0] = l.x; aL[mt2][1] = l.y; aL[mt2][2] = l.z; aL[mt2][3] = l.w;
            }
#pragma unroll
            for (int nt4 = 0; nt4 < 4; nt4++) {
                int nt = warp_n * 4 + nt4;
                uint2 h = *(const uint2*)&BsH[nt][ks][lane][0];
                uint2 l = *(const uint2*)&BsL[nt][ks][lane][0];
                bH[nt4][0] = h.x; bH[nt4][1] = h.y;
                bL[nt4][0] = l.x; bL[nt4][1] = l.y;
            }
#pragma unroll
            for (int mt2 = 0; mt2 < 2; mt2++)
#pragma unroll
                for (int nt4 = 0; nt4 < 4; nt4++) {
                    mma16816(acc[mt2][nt4], aH[mt2], bH[nt4]);
                    mma16816(acc[mt2][nt4], aH[mt2], bL[nt4]);
                    mma16816(acc[mt2][nt4], aL[mt2], bH[nt4]);
                }
        }
        __syncthreads();
    }

    // ---- epilogue ----
    int g   = lane >> 2;     // 0..7
    int tig = lane & 3;      // 0..3
#pragma unroll
    for (int mt2 = 0; mt2 < 2; mt2++) {
#pragma unroll
        for (int nt4 = 0; nt4 < 4; nt4++) {
            int cbase = bn + (warp_n * 4 + nt4) * 8 + tig * 2;
            if (cbase >= N) continue;        // N always even -> pair-aligned
#pragma unroll
            for (int h = 0; h < 2; h++) {
                int row = bm + (warp_m * 2 + mt2) * 16 + g + 8 * h;
                if (row >= M) continue;
                float v0 = acc[mt2][nt4][2 * h];
                float v1 = acc[mt2][nt4][2 * h + 1];
                if (bias) { v0 += bias[cbase]; v1 += bias[cbase + 1]; }
                if (act == 1)      { v0 = sp2f(v0); v1 = sp2f(v1); }
                else if (act == 2) { v0 = sspf(v0); v1 = sspf(v1); }
                float* cp = C + (size_t)row * N + cbase;
                if (flags & FLAG_BETA) {
                    float2 old = *(const float2*)cp;
                    v0 += old.x; v1 += old.y;
                }
                float2 st; st.x = v0; st.y = v1;
                *(float2*)cp = st;
            }
        }
    }
}

// ---------------- driver ----------------------------------------------------
static inline dim3 gemm_grid(int M, int N) {
    return dim3((N + BN - 1) / BN, (M + BM - 1) / BM);
}

extern "C" void kernel_launch(void* const* d_in, const int* in_sizes, int n_in,
                              void* d_out, int out_size) {
    const int*   node_types = (const int*)  d_in[0];
    const int*   edge_src   = (const int*)  d_in[1];
    const int*   edge_dst   = (const int*)  d_in[2];
    const int*   graph_ids  = (const int*)  d_in[3];
    const float* distance   = (const float*)d_in[4];
    const float* emb        = (const float*)d_in[5];
    const float* conv_w1    = (const float*)d_in[6];
    const float* cf1_w      = (const float*)d_in[7];
    const float* cf1_b      = (const float*)d_in[8];
    const float* cf2_w      = (const float*)d_in[9];
    const float* cf2_b      = (const float*)d_in[10];
    const float* nl2_w      = (const float*)d_in[11];
    const float* nl2_b      = (const float*)d_in[12];
    const float* nl3_w      = (const float*)d_in[13];
    const float* nl3_b      = (const float*)d_in[14];
    const float* d1_w       = (const float*)d_in[15];
    const float* d1_b       = (const float*)d_in[16];
    const float* d2_w       = (const float*)d_in[17];
    const float* d2_b       = (const float*)d_in[18];
    const float* cls_w      = (const float*)d_in[19];
    const float* cls_b      = (const float*)d_in[20];
    const float* ac_w       = (const float*)d_in[21];
    const float* ac_b       = (const float*)d_in[22];
    float* out = (float*)d_out;

    float *node, *newnode, *agg, *atom, *res, *table, *gsum, *gcnt, *gmean;
    cudaGetSymbolAddress((void**)&node,    g_node);
    cudaGetSymbolAddress((void**)&newnode, g_newnode);
    cudaGetSymbolAddress((void**)&agg,     g_agg);
    cudaGetSymbolAddress((void**)&atom,    g_atom);
    cudaGetSymbolAddress((void**)&res,     g_res);
    cudaGetSymbolAddress((void**)&table,   g_table);
    cudaGetSymbolAddress((void**)&gsum,    g_gsum);
    cudaGetSymbolAddress((void**)&gcnt,    g_gcnt);
    cudaGetSymbolAddress((void**)&gmean,   g_gmean);

    // node = emb[node_types]
    embed_kernel<<<(NN * DIM + 255) / 256, 256>>>(node_types, emb, node);

    // per-layer eh(d) lookup tables
    build_table_kernel<<<3 * TABLE_N, DIM>>>(cf1_w, cf1_b, cf2_w, cf2_b, table);

    dim3 g64 = gemm_grid(NN, DIM);
    for (int l = 0; l < 3; l++) {
        // newnode = node @ w1
        sgemm_kernel<<<g64, 256>>>(node, conv_w1 + (size_t)l * DIM * DIM,
                                   nullptr, newnode, NN, DIM, DIM, 0, 0);
        // agg = 0
        zero_kernel<<<(NN * DIM + 255) / 256, 256>>>(agg, NN * DIM);
        // agg[dst] += newnode[src] * eh(d)
        edge_kernel<<<(NE * 16 + 255) / 256, 256>>>(
            edge_src, edge_dst, distance, newnode,
            table + (size_t)l * TABLE_N * DIM, agg);
        // t = sp2(agg @ nl2 + b2)   (reuse newnode as t)
        sgemm_kernel<<<g64, 256>>>(agg, nl2_w + (size_t)l * DIM * DIM,
                                   nl2_b + l * DIM, newnode, NN, DIM, DIM, 1, 0);
        // node += t @ nl3 + b3
        sgemm_kernel<<<g64, 256>>>(newnode, nl3_w + (size_t)l * DIM * DIM,
                                   nl3_b + l * DIM, node, NN, DIM, DIM, 0, FLAG_BETA);
    }

    // atom = ssp(node @ d1 + b)
    sgemm_kernel<<<gemm_grid(NN, HID), 256>>>(node, d1_w, d1_b, atom,
                                              NN, HID, DIM, 2, 0);
    // res = atom @ d2 + b
    sgemm_kernel<<<gemm_grid(NN, HID), 256>>>(atom, d2_w, d2_b, res,
                                              NN, HID, HID, 0, 0);
    // atoms_preds = relu(res) @ ac + b   -> out[0 : NN*100]
    sgemm_kernel<<<gemm_grid(NN, NAT), 256>>>(res, ac_w, ac_b, out,
                                              NN, NAT, HID, 0, FLAG_RELUA);

    // graph pooling
    zero_kernel<<<(NG * HID + 255) / 256, 256>>>(gsum, NG * HID);
    zero_kernel<<<(NG + 255) / 256, 256>>>(gcnt, NG);
    pool_kernel<<<(NN * (HID / 2) + 255) / 256, 256>>>(graph_ids, res, gsum);
    count_kernel<<<(NN + 255) / 256, 256>>>(graph_ids, gcnt);
    mean_kernel<<<(NG * HID + 255) / 256, 256>>>(gsum, gcnt, gmean);

    // cls_preds = gmean @ cls_w + b -> out[NN*100 : ]
    sgemm_kernel<<<gemm_grid(NG, NCLS), 256>>>(gmean, cls_w, cls_b,
                                               out + (size_t)NN * NAT,
                                               NG, NCLS, HID, 0, 0);
}

// round 16
// speedup vs baseline: 1.8311x; 1.0984x over previous
#include <cuda_runtime.h>
#include <cuda_bf16.h>
#include <cuda_fp16.h>
#include <math.h>
#include <stdint.h>

#define NN      50000
#define NE      800000
#define NG      500
#define DIM     64
#define HID     256
#define NCLS    2000
#define NAT     100
#define TABLE_N 1025
#define CUTOFF  5.0f

#define FLAG_BETA  1
#define FLAG_RELUA 2

// ---------------- scratch (device globals; no allocation allowed) ----------
__device__ float g_node[NN * DIM];
__device__ float g_newnode[NN * DIM];   // also reused as t-buffer
__device__ float g_agg[NN * DIM];
__device__ float g_atom[NN * HID];
__device__ float g_res[NN * HID];
__device__ __half g_table[3 * TABLE_N * DIM];
__device__ float g_gsum[NG * HID];
__device__ float g_gcnt[NG];
__device__ float g_gmean[NG * HID];

// ---------------- activations ---------------------------------------------
__device__ __forceinline__ float softplusf(float x) {
    return fmaxf(x, 0.0f) + log1pf(expf(-fabsf(x)));
}
__device__ __forceinline__ float sp2f(float x) {       // 2*softplus(0.5x)
    return 2.0f * softplusf(0.5f * x);
}
__device__ __forceinline__ float sspf(float x) {       // softplus(x) - ln2
    return softplusf(x) - 0.69314718055994531f;
}

// ---------------- tiny utility kernels -------------------------------------
__global__ void zero4_kernel(float4* __restrict__ p, int n4) {
    int i = blockIdx.x * blockDim.x + threadIdx.x;
    if (i < n4) p[i] = make_float4(0.f, 0.f, 0.f, 0.f);
}

__global__ void embed_kernel(const int* __restrict__ types,
                             const float* __restrict__ emb,
                             float* __restrict__ node) {
    int i = blockIdx.x * blockDim.x + threadIdx.x;
    if (i >= NN * DIM) return;
    int n = i >> 6;      // /64
    int c = i & 63;
    node[i] = emb[types[n] * DIM + c];
}

// eh(d) table per layer: sp2(sp2(rbf(d)@cf1 + b1)@cf2 + b2), stored fp16
__global__ void build_table_kernel(const float* __restrict__ cf1_w,  // [3,5,64]
                                   const float* __restrict__ cf1_b,  // [3,64]
                                   const float* __restrict__ cf2_w,  // [3,64,64]
                                   const float* __restrict__ cf2_b,  // [3,64]
                                   __half* __restrict__ table) {
    __shared__ float h[DIM];
    int b = blockIdx.x;
    int layer = b / TABLE_N;
    int ent   = b % TABLE_N;
    int j = threadIdx.x;

    const float gap = CUTOFF / 4.0f;                 // linspace(0,5,5) gap = 1.25
    float d = (float)ent * (CUTOFF / (float)(TABLE_N - 1));

    float rbf[5];
#pragma unroll
    for (int r = 0; r < 5; r++) {
        float t = d - (float)r * gap;
        rbf[r] = expf(-(1.0f / gap) * t * t);
    }
    float acc = cf1_b[layer * DIM + j];
#pragma unroll
    for (int r = 0; r < 5; r++)
        acc += rbf[r] * cf1_w[(layer * 5 + r) * DIM + j];
    h[j] = sp2f(acc);
    __syncthreads();

    float acc2 = cf2_b[layer * DIM + j];
    const float* W = cf2_w + layer * DIM * DIM;
#pragma unroll 8
    for (int k = 0; k < DIM; k++)
        acc2 += h[k] * W[k * DIM + j];
    table[(layer * TABLE_N + ent) * DIM + j] = __float2half(sp2f(acc2));
}

// 16 lanes per edge; each lane handles 4 consecutive floats.
// Table is fp16, 1025x64 per layer (131 KB) -> L1-resident random access.
__global__ void edge_kernel(const int* __restrict__ src,
                            const int* __restrict__ dst,
                            const float* __restrict__ dist,
                            const float* __restrict__ newnode,
                            const __half* __restrict__ table,   // [TABLE_N,64]
                            float* __restrict__ agg) {
    int idx = blockIdx.x * blockDim.x + threadIdx.x;
    int e = idx >> 4;
    if (e >= NE) return;
    int lane = idx & 15;

    int s = __ldg(src + e);
    int t = __ldg(dst + e);
    float dd = __ldg(dist + e);

    float f = dd * ((float)(TABLE_N - 1) / CUTOFF);
    f = fminf(fmaxf(f, 0.0f), (float)(TABLE_N - 1));
    int i0 = (int)f;
    if (i0 > TABLE_N - 2) i0 = TABLE_N - 2;
    float fr = f - (float)i0;

    const float4* nn = (const float4*)(newnode + (size_t)s * DIM);
    float4 a = nn[lane];

    // two adjacent fp16 rows; 8B per lane per row
    const uint2* t0p = (const uint2*)(table + (size_t)i0 * DIM) + lane;
    uint2 r0 = __ldg(t0p);
    uint2 r1 = __ldg(t0p + 16);    // +64 halfs = +16 uint2

    __half2 h00 = *(__half2*)&r0.x, h01 = *(__half2*)&r0.y;
    __half2 h10 = *(__half2*)&r1.x, h11 = *(__half2*)&r1.y;
    float2 u0a = __half22float2(h00), u0b = __half22float2(h01);
    float2 u1a = __half22float2(h10), u1b = __half22float2(h11);

    float m0 = a.x * fmaf(fr, u1a.x - u0a.x, u0a.x);
    float m1 = a.y * fmaf(fr, u1a.y - u0a.y, u0a.y);
    float m2 = a.z * fmaf(fr, u1b.x - u0b.x, u0b.x);
    float m3 = a.w * fmaf(fr, u1b.y - u0b.y, u0b.y);

    float* out = agg + (size_t)t * DIM + lane * 4;
    asm volatile("red.global.add.v4.f32 [%0], {%1, %2, %3, %4};"
                 :: "l"(out), "f"(m0), "f"(m1), "f"(m2), "f"(m3) : "memory");
}

// graph pooling: accumulate res rows into per-graph sums
__global__ void pool_kernel(const int* __restrict__ gid,
                            const float* __restrict__ res,
                            float* __restrict__ gsum) {
    int idx = blockIdx.x * blockDim.x + threadIdx.x;   // NN * 128 threads
    if (idx >= NN * (HID / 2)) return;
    int n  = idx >> 7;        // /128
    int c2 = idx & 127;
    int g = __ldg(gid + n);
    const float2 v = ((const float2*)(res + (size_t)n * HID))[c2];
    float* out = gsum + (size_t)g * HID + c2 * 2;
    asm volatile("red.global.add.v2.f32 [%0], {%1, %2};"
                 :: "l"(out), "f"(v.x), "f"(v.y) : "memory");
}

__global__ void count_kernel(const int* __restrict__ gid, float* __restrict__ gcnt) {
    int i = blockIdx.x * blockDim.x + threadIdx.x;
    if (i < NN) atomicAdd(&gcnt[gid[i]], 1.0f);
}

__global__ void mean_kernel(const float* __restrict__ gsum,
                            const float* __restrict__ gcnt,
                            float* __restrict__ gmean) {
    int i = blockIdx.x * blockDim.x + threadIdx.x;
    if (i >= NG * HID) return;
    int g = i >> 8;   // /256
    gmean[i] = gsum[i] / fmaxf(gcnt[g], 1.0f);
}

// ---------------- tensor-core GEMM: bf16 split (hi/lo), mma.m16n8k16 --------
// (unchanged from R15 best)
#define BM 128
#define BN 64
#define KC 32

__device__ __forceinline__ uint32_t bf16x2(float lo, float hi_) {
    __nv_bfloat162 h;
    h.x = __float2bfloat16(lo);
    h.y = __float2bfloat16(hi_);
    uint32_t r;
    memcpy(&r, &h, 4);
    return r;
}

__device__ __forceinline__ void mma16816(float* c, const uint32_t* a, const uint32_t* b) {
    asm volatile(
        "mma.sync.aligned.m16n8k16.row.col.f32.bf16.bf16.f32 "
        "{%0,%1,%2,%3}, {%4,%5,%6,%7}, {%8,%9}, {%0,%1,%2,%3};"
        : "+f"(c[0]), "+f"(c[1]), "+f"(c[2]), "+f"(c[3])
        : "r"(a[0]), "r"(a[1]), "r"(a[2]), "r"(a[3]), "r"(b[0]), "r"(b[1]));
}

__global__ __launch_bounds__(256)
void sgemm_kernel(const float* __restrict__ A,
                  const float* __restrict__ B,
                  const float* __restrict__ bias,
                  float* __restrict__ C,
                  int M, int N, int K, int act, int flags) {
    __shared__ uint32_t AsH[8][2][32][4];
    __shared__ uint32_t AsL[8][2][32][4];
    __shared__ uint32_t BsH[8][2][32][2];
    __shared__ uint32_t BsL[8][2][32][2];

    int bm = blockIdx.y * BM;
    int bn = blockIdx.x * BN;
    int tid  = threadIdx.x;
    int wid  = tid >> 5;
    int lane = tid & 31;
    int warp_m = wid & 3;
    int warp_n = wid >> 2;

    float acc[2][4][4];
#pragma unroll
    for (int i = 0; i < 2; i++)
#pragma unroll
        for (int j = 0; j < 4; j++)
#pragma unroll
            for (int c = 0; c < 4; c++) acc[i][j][c] = 0.0f;

    const bool reluA = (flags & FLAG_RELUA) != 0;

    for (int k0 = 0; k0 < K; k0 += KC) {
#pragma unroll
        for (int q = 0; q < 4; q++) {
            int m  = q * 32 + (tid >> 3);
            int kf = (tid & 7) * 4;
            int gr = bm + m;
            float4 v = make_float4(0.f, 0.f, 0.f, 0.f);
            if (gr < M)
                v = *(const float4*)(A + (size_t)gr * K + k0 + kf);
            if (reluA) {
                v.x = fmaxf(v.x, 0.f); v.y = fmaxf(v.y, 0.f);
                v.z = fmaxf(v.z, 0.f); v.w = fmaxf(v.w, 0.f);
            }
            int mt = m >> 4, mh = m & 15;
            int ks = kf >> 4, kk = kf & 15;
            float xs[4] = {v.x, v.y, v.z, v.w};
#pragma unroll
            for (int p = 0; p < 2; p++) {
                int kh = kk + 2 * p;
                int l2 = (mh & 7) * 4 + ((kh & 7) >> 1);
                int s  = (mh >> 3) | ((kh >> 3) << 1);
                float x = xs[2 * p], y = xs[2 * p + 1];
                __nv_bfloat16 xh = __float2bfloat16(x);
                __nv_bfloat16 yh = __float2bfloat16(y);
                float xr = x - __bfloat162float(xh);
                float yr = y - __bfloat162float(yh);
                __nv_bfloat162 hh; hh.x = xh; hh.y = yh;
                uint32_t uh; memcpy(&uh, &hh, 4);
                AsH[mt][ks][l2][s] = uh;
                AsL[mt][ks][l2][s] = bf16x2(xr, yr);
            }
        }
#pragma unroll
        for (int r = 0; r < 4; r++) {
            int pi = tid + 256 * r;
            int n  = pi & 63;
            int k2 = (pi >> 6) << 1;
            int gc = bn + n;
            float x = 0.f, y = 0.f;
            if (gc < N) {
                int gk = k0 + k2;
                x = B[(size_t)gk * N + gc];
                y = B[(size_t)(gk + 1) * N + gc];
            }
            __nv_bfloat16 xh = __float2bfloat16(x);
            __nv_bfloat16 yh = __float2bfloat16(y);
            float xr = x - __bfloat162float(xh);
            float yr = y - __bfloat162float(yh);
            int nt = n >> 3, nh = n & 7;
            int ks = k2 >> 4, kk = k2 & 15;
            int l2 = nh * 4 + ((kk & 7) >> 1);
            int s  = kk >> 3;
            __nv_bfloat162 hh; hh.x = xh; hh.y = yh;
            uint32_t uh; memcpy(&uh, &hh, 4);
            BsH[nt][ks][l2][s] = uh;
            BsL[nt][ks][l2][s] = bf16x2(xr, yr);
        }
        __syncthreads();

#pragma unroll
        for (int ks = 0; ks < 2; ks++) {
            uint32_t aH[2][4], aL[2][4], bH[4][2], bL[4][2];
#pragma unroll
            for (int mt2 = 0; mt2 < 2; mt2++) {
                int mt = warp_m * 2 + mt2;
                uint4 h = *(const uint4*)&AsH[mt][ks][lane][0];
                uint4 l = *(const uint4*)&AsL[mt][ks][lane][0];
                aH[mt2][0] = h.x; aH[mt2][1] = h.y; aH[mt2][2] = h.z; aH[mt2][3] = h.w;
                aL[mt2][0] = l.x; aL[mt2][1] = l.y; aL[mt2][2] = l.z; aL[mt2][3] = l.w;
            }
#pragma unroll
            for (int nt4 = 0; nt4 < 4; nt4++) {
                int nt = warp_n * 4 + nt4;
                uint2 h = *(const uint2*)&BsH[nt][ks][lane][0];
                uint2 l = *(const uint2*)&BsL[nt][ks][lane][0];
                bH[nt4][0] = h.x; bH[nt4][1] = h.y;
                bL[nt4][0] = l.x; bL[nt4][1] = l.y;
            }
#pragma unroll
            for (int mt2 = 0; mt2 < 2; mt2++)
#pragma unroll
                for (int nt4 = 0; nt4 < 4; nt4++) {
                    mma16816(acc[mt2][nt4], aH[mt2], bH[nt4]);
                    mma16816(acc[mt2][nt4], aH[mt2], bL[nt4]);
                    mma16816(acc[mt2][nt4], aL[mt2], bH[nt4]);
                }
        }
        __syncthreads();
    }

    int g   = lane >> 2;
    int tig = lane & 3;
#pragma unroll
    for (int mt2 = 0; mt2 < 2; mt2++) {
#pragma unroll
        for (int nt4 = 0; nt4 < 4; nt4++) {
            int cbase = bn + (warp_n * 4 + nt4) * 8 + tig * 2;
            if (cbase >= N) continue;
#pragma unroll
            for (int h = 0; h < 2; h++) {
                int row = bm + (warp_m * 2 + mt2) * 16 + g + 8 * h;
                if (row >= M) continue;
                float v0 = acc[mt2][nt4][2 * h];
                float v1 = acc[mt2][nt4][2 * h + 1];
                if (bias) { v0 += bias[cbase]; v1 += bias[cbase + 1]; }
                if (act == 1)      { v0 = sp2f(v0); v1 = sp2f(v1); }
                else if (act == 2) { v0 = sspf(v0); v1 = sspf(v1); }
                float* cp = C + (size_t)row * N + cbase;
                if (flags & FLAG_BETA) {
                    float2 old = *(const float2*)cp;
                    v0 += old.x; v1 += old.y;
                }
                float2 st; st.x = v0; st.y = v1;
                *(float2*)cp = st;
            }
        }
    }
}

// ---------------- driver ----------------------------------------------------
static inline dim3 gemm_grid(int M, int N) {
    return dim3((N + BN - 1) / BN, (M + BM - 1) / BM);
}

extern "C" void kernel_launch(void* const* d_in, const int* in_sizes, int n_in,
                              void* d_out, int out_size) {
    const int*   node_types = (const int*)  d_in[0];
    const int*   edge_src   = (const int*)  d_in[1];
    const int*   edge_dst   = (const int*)  d_in[2];
    const int*   graph_ids  = (const int*)  d_in[3];
    const float* distance   = (const float*)d_in[4];
    const float* emb        = (const float*)d_in[5];
    const float* conv_w1    = (const float*)d_in[6];
    const float* cf1_w      = (const float*)d_in[7];
    const float* cf1_b      = (const float*)d_in[8];
    const float* cf2_w      = (const float*)d_in[9];
    const float* cf2_b      = (const float*)d_in[10];
    const float* nl2_w      = (const float*)d_in[11];
    const float* nl2_b      = (const float*)d_in[12];
    const float* nl3_w      = (const float*)d_in[13];
    const float* nl3_b      = (const float*)d_in[14];
    const float* d1_w       = (const float*)d_in[15];
    const float* d1_b       = (const float*)d_in[16];
    const float* d2_w       = (const float*)d_in[17];
    const float* d2_b       = (const float*)d_in[18];
    const float* cls_w      = (const float*)d_in[19];
    const float* cls_b      = (const float*)d_in[20];
    const float* ac_w       = (const float*)d_in[21];
    const float* ac_b       = (const float*)d_in[22];
    float* out = (float*)d_out;

    float *node, *newnode, *agg, *atom, *res, *gsum, *gcnt, *gmean;
    __half* table;
    cudaGetSymbolAddress((void**)&node,    g_node);
    cudaGetSymbolAddress((void**)&newnode, g_newnode);
    cudaGetSymbolAddress((void**)&agg,     g_agg);
    cudaGetSymbolAddress((void**)&atom,    g_atom);
    cudaGetSymbolAddress((void**)&res,     g_res);
    cudaGetSymbolAddress((void**)&table,   g_table);
    cudaGetSymbolAddress((void**)&gsum,    g_gsum);
    cudaGetSymbolAddress((void**)&gcnt,    g_gcnt);
    cudaGetSymbolAddress((void**)&gmean,   g_gmean);

    // node = emb[node_types]
    embed_kernel<<<(NN * DIM + 255) / 256, 256>>>(node_types, emb, node);

    // per-layer eh(d) lookup tables (fp16, L1-resident at 1025 entries)
    build_table_kernel<<<3 * TABLE_N, DIM>>>(cf1_w, cf1_b, cf2_w, cf2_b, table);

    dim3 g64 = gemm_grid(NN, DIM);
    for (int l = 0; l < 3; l++) {
        // newnode = node @ w1
        sgemm_kernel<<<g64, 256>>>(node, conv_w1 + (size_t)l * DIM * DIM,
                                   nullptr, newnode, NN, DIM, DIM, 0, 0);
        // agg = 0
        zero4_kernel<<<(NN * DIM / 4 + 255) / 256, 256>>>((float4*)agg, NN * DIM / 4);
        // agg[dst] += newnode[src] * eh(d)
        edge_kernel<<<(NE * 16 + 255) / 256, 256>>>(
            edge_src, edge_dst, distance, newnode,
            table + (size_t)l * TABLE_N * DIM, agg);
        // t = sp2(agg @ nl2 + b2)   (reuse newnode as t)
        sgemm_kernel<<<g64, 256>>>(agg, nl2_w + (size_t)l * DIM * DIM,
                                   nl2_b + l * DIM, newnode, NN, DIM, DIM, 1, 0);
        // node += t @ nl3 + b3
        sgemm_kernel<<<g64, 256>>>(newnode, nl3_w + (size_t)l * DIM * DIM,
                                   nl3_b + l * DIM, node, NN, DIM, DIM, 0, FLAG_BETA);
    }

    // atom = ssp(node @ d1 + b)
    sgemm_kernel<<<gemm_grid(NN, HID), 256>>>(node, d1_w, d1_b, atom,
                                              NN, HID, DIM, 2, 0);
    // res = atom @ d2 + b
    sgemm_kernel<<<gemm_grid(NN, HID), 256>>>(atom, d2_w, d2_b, res,
                                              NN, HID, HID, 0, 0);
    // atoms_preds = relu(res) @ ac + b   -> out[0 : NN*100]
    sgemm_kernel<<<gemm_grid(NN, NAT), 256>>>(res, ac_w, ac_b, out,
                                              NN, NAT, HID, 0, FLAG_RELUA);

    // graph pooling
    zero4_kernel<<<(NG * HID / 4 + 255) / 256, 256>>>((float4*)gsum, NG * HID / 4);
    zero4_kernel<<<(NG / 4 + 255) / 256, 256>>>((float4*)gcnt, NG / 4);
    pool_kernel<<<(NN * (HID / 2) + 255) / 256, 256>>>(graph_ids, res, gsum);
    count_kernel<<<(NN + 255) / 256, 256>>>(graph_ids, gcnt);
    mean_kernel<<<(NG * HID + 255) / 256, 256>>>(gsum, gcnt, gmean);

    // cls_preds = gmean @ cls_w + b -> out[NN*100 : ]
    sgemm_kernel<<<gemm_grid(NG, NCLS), 256>>>(gmean, cls_w, cls_b,
                                               out + (size_t)NN * NAT,
                                               NG, NCLS, HID, 0, 0);
}